// round 13
// baseline (speedup 1.0000x reference)
#include <cuda_runtime.h>
#include <cuda_bf16.h>
#include <cstdint>

#define B_   8192
#define D_   512
#define PD_  128
#define NNEG 10
#define INV_SQRT_T 1.41421356237309515f   // g = h/(||h||*sqrt(T)) so g.g' = sim
#define SIM_SCALE  60.0f                  // sim |.|<=2 -> |code| <= ~121
#define SIM_ISCALE (1.0f / 60.0f)
#define GQ_SCALE   64.0f                  // g int8 quant scale (|g_i| <= 1.42 < 127/64)
#define ACC2CODE   (SIM_SCALE / (GQ_SCALE * GQ_SCALE))   // 60/4096

// ---------------- scratch (device globals; no allocation) ----------------
static __device__ __nv_bfloat16  d_Xb [(size_t)B_ * D_];     // bf16 X, 8 MB
static __device__ __nv_bfloat16  d_W1b[(size_t)D_ * D_];     // bf16 W1
static __device__ __nv_bfloat16  d_W2b[(size_t)PD_ * D_];    // bf16 W2
static __device__ __nv_bfloat16  d_A1b[(size_t)B_ * D_];     // relu(x@w1^T), 8 MB
static __device__ __align__(16) int8_t d_gq[(size_t)B_ * PD_]; // int8 g codes, 1 MB
static __device__ int8_t         d_sim[(size_t)B_ * B_];     // full symmetric, 67 MB
static __device__ float          d_partials[65536];
static __device__ unsigned int   d_done;

__device__ __forceinline__ uint32_t smem_addr(const void* p) {
    return (uint32_t)__cvta_generic_to_shared(p);
}
#define CP_ASYNC16(dst, src) \
    asm volatile("cp.async.cg.shared.global [%0], [%1], 16;" :: "r"(dst), "l"(src))
#define CP_COMMIT() asm volatile("cp.async.commit_group;" ::: "memory")
#define CP_WAIT1()  asm volatile("cp.async.wait_group 1;" ::: "memory")

#define LDSM_X4(r0, r1, r2, r3, ad) \
    asm volatile("ldmatrix.sync.aligned.m8n8.x4.shared.b16 {%0,%1,%2,%3}, [%4];" \
                 : "=r"(r0), "=r"(r1), "=r"(r2), "=r"(r3) : "r"(ad))
#define MMA16816(acc, a, b) \
    asm volatile("mma.sync.aligned.m16n8k16.row.col.f32.bf16.bf16.f32 " \
                 "{%0,%1,%2,%3}, {%4,%5,%6,%7}, {%8,%9}, {%0,%1,%2,%3};" \
                 : "+f"((acc)[0]), "+f"((acc)[1]), "+f"((acc)[2]), "+f"((acc)[3]) \
                 : "r"((a)[0]), "r"((a)[1]), "r"((a)[2]), "r"((a)[3]), \
                   "r"((b)[0]), "r"((b)[1]))
#define MMAS8(acc, a, b) \
    asm volatile("mma.sync.aligned.m16n8k32.row.col.s32.s8.s8.s32 " \
                 "{%0,%1,%2,%3}, {%4,%5,%6,%7}, {%8,%9}, {%0,%1,%2,%3};" \
                 : "+r"((acc)[0]), "+r"((acc)[1]), "+r"((acc)[2]), "+r"((acc)[3]) \
                 : "r"((a)[0]), "r"((a)[1]), "r"((a)[2]), "r"((a)[3]), \
                   "r"((b)[0]), "r"((b)[1]))

// quantize 2 floats -> packed s8 pair in low 16 bits (byte0 = f0, byte1 = f1)
__device__ __forceinline__ uint32_t pack2_s8(float f0, float f1)
{
    int i0 = __float2int_rn(f0);
    int i1 = __float2int_rn(f1);
    uint32_t r;
    asm("cvt.pack.sat.s8.s32.b32 %0, %1, %2, 0;" : "=r"(r) : "r"(i1), "r"(i0));
    return r;
}

// =========================================================================
// Kernel 0: fp32 -> bf16 conversion of X, W1, W2 (one pass)
// =========================================================================
#define NX4  (B_ * D_ / 4)
#define NW14 (D_ * D_ / 4)
#define NW24 (PD_ * D_ / 4)
#define NCVT (NX4 + NW14 + NW24)

__global__ __launch_bounds__(256)
void convert_k(const float* __restrict__ X, const float* __restrict__ W1,
               const float* __restrict__ W2)
{
    int idx = blockIdx.x * 256 + threadIdx.x;
    if (idx >= NCVT) return;
    float4 v;
    __nv_bfloat16* dst;
    if (idx < NX4) {
        v = ((const float4*)X)[idx];
        dst = d_Xb + (size_t)idx * 4;
    } else if (idx < NX4 + NW14) {
        int j = idx - NX4;
        v = ((const float4*)W1)[j];
        dst = d_W1b + (size_t)j * 4;
    } else {
        int j = idx - NX4 - NW14;
        v = ((const float4*)W2)[j];
        dst = d_W2b + (size_t)j * 4;
    }
    __nv_bfloat162 p0 = __floats2bfloat162_rn(v.x, v.y);
    __nv_bfloat162 p1 = __floats2bfloat162_rn(v.z, v.w);
    uint2 o;
    o.x = *(uint32_t*)&p0;
    o.y = *(uint32_t*)&p1;
    *(uint2*)dst = o;
}

// =========================================================================
// Kernel 1: A1 = relu(X @ W1^T) bf16 HMMA + ldmatrix + cp.async (BK=64)
// =========================================================================
#define BSTR 72
#define G1_TILEE (128 * BSTR)
#define G1_SMEM_BYTES (4 * G1_TILEE * 2)

__global__ __launch_bounds__(256, 2)
void gemm1_bf16_k()
{
    extern __shared__ __nv_bfloat16 dynb[];
    __nv_bfloat16* Asb = dynb;
    __nv_bfloat16* Bsb = dynb + 2 * G1_TILEE;

    const int tid  = threadIdx.x;
    const int wid  = tid >> 5;
    const int lane = tid & 31;
    const int bm = blockIdx.y * 128;
    const int bn = blockIdx.x * 128;

    const int wm = (wid >> 2) * 64;
    const int wn = (wid & 3) * 32;
    const int qr = lane >> 2;
    const int qc2 = (lane & 3) * 2;

    const int a_row = lane & 15;
    const int a_kof = (lane >> 4) * 8;
    const int g3    = lane >> 3;
    const int b_row = 8 * (g3 >> 1) + (lane & 7);
    const int b_kof = 8 * (g3 & 1);

    int srow[4], scol[4];
#pragma unroll
    for (int l = 0; l < 4; l++) {
        int id = tid + l * 256;
        srow[l] = id >> 3;
        scol[l] = (id & 7) * 8;
    }

    float acc[4][4][4];
#pragma unroll
    for (int mi = 0; mi < 4; mi++)
#pragma unroll
        for (int nj = 0; nj < 4; nj++)
#pragma unroll
            for (int q = 0; q < 4; q++) acc[mi][nj][q] = 0.f;

#pragma unroll
    for (int l = 0; l < 4; l++) {
        CP_ASYNC16(smem_addr(Asb + srow[l] * BSTR + scol[l]),
                   d_Xb + (size_t)(bm + srow[l]) * D_ + scol[l]);
        CP_ASYNC16(smem_addr(Bsb + srow[l] * BSTR + scol[l]),
                   d_W1b + (size_t)(bn + srow[l]) * D_ + scol[l]);
    }
    CP_COMMIT();

    const int NIT = D_ / 64;
    for (int it = 0; it < NIT; it++) {
        if (it + 1 < NIT) {
            int kn = (it + 1) * 64;
            uint32_t boff = ((it + 1) & 1) * G1_TILEE;
#pragma unroll
            for (int l = 0; l < 4; l++) {
                CP_ASYNC16(smem_addr(Asb + boff + srow[l] * BSTR + scol[l]),
                           d_Xb + (size_t)(bm + srow[l]) * D_ + kn + scol[l]);
                CP_ASYNC16(smem_addr(Bsb + boff + srow[l] * BSTR + scol[l]),
                           d_W1b + (size_t)(bn + srow[l]) * D_ + kn + scol[l]);
            }
        }
        CP_COMMIT();
        CP_WAIT1();
        __syncthreads();

        const __nv_bfloat16* As = Asb + (it & 1) * G1_TILEE;
        const __nv_bfloat16* Bs = Bsb + (it & 1) * G1_TILEE;
#pragma unroll
        for (int ks = 0; ks < 4; ks++) {
            uint32_t a[4][4], b[4][2];
#pragma unroll
            for (int mi = 0; mi < 4; mi++) {
                uint32_t ad = smem_addr(As + (wm + 16 * mi + a_row) * BSTR
                                           + ks * 16 + a_kof);
                LDSM_X4(a[mi][0], a[mi][1], a[mi][2], a[mi][3], ad);
            }
#pragma unroll
            for (int nj2 = 0; nj2 < 2; nj2++) {
                uint32_t bd = smem_addr(Bs + (wn + 16 * nj2 + b_row) * BSTR
                                           + ks * 16 + b_kof);
                LDSM_X4(b[2 * nj2][0], b[2 * nj2][1],
                        b[2 * nj2 + 1][0], b[2 * nj2 + 1][1], bd);
            }
#pragma unroll
            for (int mi = 0; mi < 4; mi++)
#pragma unroll
                for (int nj = 0; nj < 4; nj++)
                    MMA16816(acc[mi][nj], a[mi], b[nj]);
        }
        __syncthreads();
    }

#pragma unroll
    for (int mi = 0; mi < 4; mi++)
#pragma unroll
        for (int nj = 0; nj < 4; nj++) {
            int row = bm + wm + 16 * mi + qr;
            int col = bn + wn + 8 * nj + qc2;
            __nv_bfloat162 lo = __floats2bfloat162_rn(fmaxf(acc[mi][nj][0], 0.f),
                                                      fmaxf(acc[mi][nj][1], 0.f));
            __nv_bfloat162 hi = __floats2bfloat162_rn(fmaxf(acc[mi][nj][2], 0.f),
                                                      fmaxf(acc[mi][nj][3], 0.f));
            *(__nv_bfloat162*)(d_A1b + (size_t)row * D_ + col) = lo;
            *(__nv_bfloat162*)(d_A1b + (size_t)(row + 8) * D_ + col) = hi;
        }
}

// =========================================================================
// Kernel 2: h = A1 @ W2^T bf16 HMMA, fused row-norm -> int8 g codes
// =========================================================================
#define G2_ATILEE (64 * BSTR)
#define G2_BTILEE (128 * BSTR)
#define G2_SMEM_BYTES (2 * (G2_ATILEE + G2_BTILEE) * 2)

__global__ __launch_bounds__(256, 2)
void gemm2_bf16_k()
{
    extern __shared__ __nv_bfloat16 dynb[];
    __nv_bfloat16* Asb = dynb;
    __nv_bfloat16* Bsb = dynb + 2 * G2_ATILEE;
    __shared__ float sqp[64][4];
    __shared__ float scale_s[64];

    const int tid  = threadIdx.x;
    const int wid  = tid >> 5;
    const int lane = tid & 31;
    const int bm = blockIdx.x * 64;

    const int wm = (wid >> 2) * 32;
    const int wn = (wid & 3) * 32;
    const int qr = lane >> 2;
    const int qc2 = (lane & 3) * 2;

    const int a_row = lane & 15;
    const int a_kof = (lane >> 4) * 8;
    const int g3    = lane >> 3;
    const int b_row = 8 * (g3 >> 1) + (lane & 7);
    const int b_kof = 8 * (g3 & 1);

    int srow[4], scol[4];
#pragma unroll
    for (int l = 0; l < 4; l++) {
        int id = tid + l * 256;
        srow[l] = id >> 3;
        scol[l] = (id & 7) * 8;
    }

    float acc[2][4][4];
#pragma unroll
    for (int mi = 0; mi < 2; mi++)
#pragma unroll
        for (int nj = 0; nj < 4; nj++)
#pragma unroll
            for (int q = 0; q < 4; q++) acc[mi][nj][q] = 0.f;

#pragma unroll
    for (int l = 0; l < 2; l++)
        CP_ASYNC16(smem_addr(Asb + srow[l] * BSTR + scol[l]),
                   d_A1b + (size_t)(bm + srow[l]) * D_ + scol[l]);
#pragma unroll
    for (int l = 0; l < 4; l++)
        CP_ASYNC16(smem_addr(Bsb + srow[l] * BSTR + scol[l]),
                   d_W2b + (size_t)srow[l] * D_ + scol[l]);
    CP_COMMIT();

    const int NIT = D_ / 64;
    for (int it = 0; it < NIT; it++) {
        if (it + 1 < NIT) {
            int kn = (it + 1) * 64;
            uint32_t ab = ((it + 1) & 1) * G2_ATILEE;
            uint32_t bb = ((it + 1) & 1) * G2_BTILEE;
#pragma unroll
            for (int l = 0; l < 2; l++)
                CP_ASYNC16(smem_addr(Asb + ab + srow[l] * BSTR + scol[l]),
                           d_A1b + (size_t)(bm + srow[l]) * D_ + kn + scol[l]);
#pragma unroll
            for (int l = 0; l < 4; l++)
                CP_ASYNC16(smem_addr(Bsb + bb + srow[l] * BSTR + scol[l]),
                           d_W2b + (size_t)srow[l] * D_ + kn + scol[l]);
        }
        CP_COMMIT();
        CP_WAIT1();
        __syncthreads();

        const __nv_bfloat16* As = Asb + (it & 1) * G2_ATILEE;
        const __nv_bfloat16* Bs = Bsb + (it & 1) * G2_BTILEE;
#pragma unroll
        for (int ks = 0; ks < 4; ks++) {
            uint32_t a[2][4], b[4][2];
#pragma unroll
            for (int mi = 0; mi < 2; mi++) {
                uint32_t ad = smem_addr(As + (wm + 16 * mi + a_row) * BSTR
                                           + ks * 16 + a_kof);
                LDSM_X4(a[mi][0], a[mi][1], a[mi][2], a[mi][3], ad);
            }
#pragma unroll
            for (int nj2 = 0; nj2 < 2; nj2++) {
                uint32_t bd = smem_addr(Bs + (wn + 16 * nj2 + b_row) * BSTR
                                           + ks * 16 + b_kof);
                LDSM_X4(b[2 * nj2][0], b[2 * nj2][1],
                        b[2 * nj2 + 1][0], b[2 * nj2 + 1][1], bd);
            }
#pragma unroll
            for (int mi = 0; mi < 2; mi++)
#pragma unroll
                for (int nj = 0; nj < 4; nj++)
                    MMA16816(acc[mi][nj], a[mi], b[nj]);
        }
        __syncthreads();
    }

#pragma unroll
    for (int mi = 0; mi < 2; mi++) {
        float s0 = 0.f, s1 = 0.f;
#pragma unroll
        for (int nj = 0; nj < 4; nj++) {
            s0 = fmaf(acc[mi][nj][0], acc[mi][nj][0], s0);
            s0 = fmaf(acc[mi][nj][1], acc[mi][nj][1], s0);
            s1 = fmaf(acc[mi][nj][2], acc[mi][nj][2], s1);
            s1 = fmaf(acc[mi][nj][3], acc[mi][nj][3], s1);
        }
        s0 += __shfl_xor_sync(0xffffffffu, s0, 1);
        s0 += __shfl_xor_sync(0xffffffffu, s0, 2);
        s1 += __shfl_xor_sync(0xffffffffu, s1, 1);
        s1 += __shfl_xor_sync(0xffffffffu, s1, 2);
        if ((lane & 3) == 0) {
            sqp[wm + 16 * mi + qr][wid & 3]     = s0;
            sqp[wm + 16 * mi + qr + 8][wid & 3] = s1;
        }
    }
    __syncthreads();
    if (tid < 64) {
        float ss = sqp[tid][0] + sqp[tid][1] + sqp[tid][2] + sqp[tid][3];
        scale_s[tid] = rsqrtf(fmaxf(ss, 1e-24f)) * INV_SQRT_T * GQ_SCALE;
    }
    __syncthreads();

    // epilogue: int8 g codes (scale 64), 2B stores
#pragma unroll
    for (int mi = 0; mi < 2; mi++)
#pragma unroll
        for (int nj = 0; nj < 4; nj++) {
            int r0 = wm + 16 * mi + qr;
            int col = wn + 8 * nj + qc2;
            float sc0 = scale_s[r0];
            float sc1 = scale_s[r0 + 8];
            uint32_t plo = pack2_s8(acc[mi][nj][0] * sc0, acc[mi][nj][1] * sc0);
            uint32_t phi = pack2_s8(acc[mi][nj][2] * sc1, acc[mi][nj][3] * sc1);
            *(uint16_t*)(d_gq + (size_t)(bm + r0) * PD_ + col) = (uint16_t)plo;
            *(uint16_t*)(d_gq + (size_t)(bm + r0 + 8) * PD_ + col) = (uint16_t)phi;
        }
}

// =========================================================================
// Kernel 3: Gram via INT8 MMA (m16n8k32.s8), triangular grid, 256 threads,
// 2x4 warps, 64x32 warp tile. K=128 int8 = 128B rows, stride 144, 4 ks.
// sim_code = round(acc * 60/4096). Symmetric store via int8 SMEM staging.
// =========================================================================
#define GSTR 144                          // int8 tile row stride (bytes)
#define GTILE (128 * GSTR)                // 18432 B per tile
#define ESTR 136
#define GRAM_SMEM_BYTES (2 * GTILE)       // 36864 B

__global__ __launch_bounds__(256, 2)
void gram_k()
{
    // triangular map: t -> (by, bx), bx >= by, 64x64 tile grid
    int t = blockIdx.x;
    int by = (int)(64.5f - sqrtf(64.5f * 64.5f - 2.0f * (float)t));
    while (by * 64 - by * (by - 1) / 2 > t) by--;
    while ((by + 1) * 64 - (by + 1) * by / 2 <= t) by++;
    int bx = by + (t - (by * 64 - by * (by - 1) / 2));

    extern __shared__ __align__(16) int8_t smi[];
    int8_t* As = smi;
    int8_t* Bs = smi + GTILE;

    const int tid  = threadIdx.x;
    const int wid  = tid >> 5;
    const int lane = tid & 31;
    const int m0 = by * 128;
    const int n0 = bx * 128;
    const bool diag = (bx == by);

    // load int8 tiles: 128 rows x 128B, uint4 chunks (8 per row)
    const uint4* grow = (const uint4*)d_gq;
#pragma unroll
    for (int i = 0; i < 4; i++) {
        int id = tid + i * 256;              // 0..1023
        int r  = id >> 3;
        int ch = id & 7;
        uint4 va = grow[(size_t)(m0 + r) * 8 + ch];
        uint4 vb = grow[(size_t)(n0 + r) * 8 + ch];
        *(uint4*)(As + r * GSTR + ch * 16) = va;
        *(uint4*)(Bs + r * GSTR + ch * 16) = vb;
    }
    __syncthreads();

    const int wm = (wid >> 2) * 64;
    const int wn = (wid & 3) * 32;
    const int qr = lane >> 2;
    const int qc = (lane & 3) * 2;

    // ldmatrix lane addressing (BYTE offsets — identical scheme to bf16)
    const int a_row = lane & 15;
    const int a_kof = (lane >> 4) * 16;      // bytes
    const int g3    = lane >> 3;
    const int b_row = 8 * (g3 >> 1) + (lane & 7);
    const int b_kof = 16 * (g3 & 1);         // bytes

    int acc[4][4][4];
#pragma unroll
    for (int mi = 0; mi < 4; mi++)
#pragma unroll
        for (int nj = 0; nj < 4; nj++)
#pragma unroll
            for (int q = 0; q < 4; q++) acc[mi][nj][q] = 0;

#pragma unroll
    for (int ks = 0; ks < 4; ks++) {         // 4 x K=32
        uint32_t a[4][4], b[4][2];
#pragma unroll
        for (int mi = 0; mi < 4; mi++) {
            uint32_t ad = smem_addr(As + (wm + 16 * mi + a_row) * GSTR
                                       + ks * 32 + a_kof);
            LDSM_X4(a[mi][0], a[mi][1], a[mi][2], a[mi][3], ad);
        }
#pragma unroll
        for (int nj2 = 0; nj2 < 2; nj2++) {
            uint32_t bd = smem_addr(Bs + (wn + 16 * nj2 + b_row) * GSTR
                                       + ks * 32 + b_kof);
            LDSM_X4(b[2 * nj2][0], b[2 * nj2][1],
                    b[2 * nj2 + 1][0], b[2 * nj2 + 1][1], bd);
        }
#pragma unroll
        for (int mi = 0; mi < 4; mi++)
#pragma unroll
            for (int nj = 0; nj < 4; nj++)
                MMAS8(acc[mi][nj], a[mi], b[nj]);
    }

    // ---- single-pass int8 staging: primary tile + transposed mirror ----
    __syncthreads();
    int8_t* ES  = smi;                       // [128][ESTR] (m-major)
    int8_t* EST = smi + 128 * ESTR;          // [128][ESTR] (n-major mirror)

#pragma unroll
    for (int mi = 0; mi < 4; mi++)
#pragma unroll
        for (int nj = 0; nj < 4; nj++) {
            int r0 = wm + 16 * mi + qr;
            int c0 = wn + 8 * nj + qc;
            uint32_t plo = pack2_s8((float)acc[mi][nj][0] * ACC2CODE,
                                    (float)acc[mi][nj][1] * ACC2CODE);
            uint32_t phi = pack2_s8((float)acc[mi][nj][2] * ACC2CODE,
                                    (float)acc[mi][nj][3] * ACC2CODE);
            *(uint16_t*)(ES + r0 * ESTR + c0)       = (uint16_t)plo;
            *(uint16_t*)(ES + (r0 + 8) * ESTR + c0) = (uint16_t)phi;
            if (!diag) {
                EST[c0 * ESTR + r0]           = (int8_t)(plo & 0xff);
                EST[(c0 + 1) * ESTR + r0]     = (int8_t)((plo >> 8) & 0xff);
                EST[c0 * ESTR + r0 + 8]       = (int8_t)(phi & 0xff);
                EST[(c0 + 1) * ESTR + r0 + 8] = (int8_t)((phi >> 8) & 0xff);
            }
        }
    __syncthreads();

    // ---- pure copy-outs (8B per thread-iter, fully coalesced) ----
#pragma unroll
    for (int i = 0; i < 8; i++) {
        int id = tid + i * 256;
        int r  = id >> 4;
        int ch = id & 15;
        uint2 v = *(const uint2*)(ES + r * ESTR + ch * 8);
        *(uint2*)(d_sim + (size_t)(m0 + r) * B_ + n0 + ch * 8) = v;
    }
    if (!diag) {
#pragma unroll
        for (int i = 0; i < 8; i++) {
            int id = tid + i * 256;
            int r  = id >> 4;
            int ch = id & 15;
            uint2 v = *(const uint2*)(EST + r * ESTR + ch * 8);
            *(uint2*)(d_sim + (size_t)(n0 + r) * B_ + m0 + ch * 8) = v;
        }
    }
}

// =========================================================================
// Kernel 4: gather + table-based logsumexp + fused deterministic finalize
// =========================================================================
__global__ __launch_bounds__(256)
void gather_lse_k(const int* __restrict__ anchors,
                  const int* __restrict__ positives,
                  const int* __restrict__ negidx,
                  int npairs, float* __restrict__ out)
{
    __shared__ float etab[256];
    __shared__ float ws[8];
    __shared__ int is_last;

    const int tid = threadIdx.x;
    etab[tid] = __expf((float)(tid - 128) * SIM_ISCALE);
    __syncthreads();

    const int p = blockIdx.x * 256 + tid;
    const bool valid = (p < npairs);
    const int pc = valid ? p : 0;

    const int a = anchors[pc];
    const int8_t* __restrict__ row = d_sim + (size_t)a * B_;
    int pidx = positives[pc];
    int nid[NNEG];
#pragma unroll
    for (int j = 0; j < NNEG; j++) nid[j] = negidx[(size_t)pc * NNEG + j];

    int cp = (int)row[pidx];
    float sum = etab[cp + 128];
#pragma unroll
    for (int j = 0; j < NNEG; j++) sum += etab[(int)row[nid[j]] + 128];

    float contrib = valid ? (__logf(sum) - (float)cp * SIM_ISCALE) : 0.f;

    contrib += __shfl_xor_sync(0xffffffffu, contrib, 1);
    contrib += __shfl_xor_sync(0xffffffffu, contrib, 2);
    contrib += __shfl_xor_sync(0xffffffffu, contrib, 4);
    contrib += __shfl_xor_sync(0xffffffffu, contrib, 8);
    contrib += __shfl_xor_sync(0xffffffffu, contrib, 16);
    if ((tid & 31) == 0) ws[tid >> 5] = contrib;
    __syncthreads();
    if (tid < 8) {
        float cv = ws[tid];
        cv += __shfl_xor_sync(0xffu, cv, 1);
        cv += __shfl_xor_sync(0xffu, cv, 2);
        cv += __shfl_xor_sync(0xffu, cv, 4);
        if (tid == 0) d_partials[blockIdx.x] = cv;
    }

    if (tid == 0) {
        __threadfence();
        unsigned t = atomicAdd(&d_done, 1u);
        is_last = (t == gridDim.x - 1);
    }
    __syncthreads();
    if (is_last) {
        __shared__ float sm[256];
        float s = 0.f;
        for (int i = tid; i < (int)gridDim.x; i += 256) s += d_partials[i];
        sm[tid] = s;
        __syncthreads();
        for (int w = 128; w > 0; w >>= 1) {
            if (tid < w) sm[tid] += sm[tid + w];
            __syncthreads();
        }
        if (tid == 0) {
            out[0] = sm[0] / (float)npairs;
            d_done = 0;
        }
    }
}

// =========================================================================
extern "C" void kernel_launch(void* const* d_in, const int* in_sizes, int n_in,
                              void* d_out, int out_size)
{
    const float* x        = (const float*)d_in[0];
    const float* w1       = (const float*)d_in[1];
    const float* w2       = (const float*)d_in[2];
    const int*   anchors  = (const int*)d_in[4];
    const int*   positives= (const int*)d_in[5];
    const int*   negidx   = (const int*)d_in[6];
    const int npairs = in_sizes[4];

    static int attrs_set = 0;
    if (!attrs_set) {
        cudaFuncSetAttribute(gemm1_bf16_k,
                             cudaFuncAttributeMaxDynamicSharedMemorySize, G1_SMEM_BYTES);
        cudaFuncSetAttribute(gemm2_bf16_k,
                             cudaFuncAttributeMaxDynamicSharedMemorySize, G2_SMEM_BYTES);
        cudaFuncSetAttribute(gram_k,
                             cudaFuncAttributeMaxDynamicSharedMemorySize, GRAM_SMEM_BYTES);
        attrs_set = 1;
    }

    convert_k<<<(NCVT + 255) / 256, 256>>>(x, w1, w2);

    dim3 g1(D_ / 128, B_ / 128);
    gemm1_bf16_k<<<g1, 256, G1_SMEM_BYTES>>>();

    gemm2_bf16_k<<<B_ / 64, 256, G2_SMEM_BYTES>>>();

    gram_k<<<2080, 256, GRAM_SMEM_BYTES>>>();   // 64*65/2 upper tiles

    int pblocks = (npairs + 255) / 256;
    gather_lse_k<<<pblocks, 256>>>(anchors, positives, negidx, npairs,
                                   (float*)d_out);
}

// round 15
// speedup vs baseline: 1.2203x; 1.2203x over previous
#include <cuda_runtime.h>
#include <cuda_bf16.h>
#include <cstdint>

#define B_   8192
#define D_   512
#define PD_  128
#define NNEG 10
#define INV_SQRT_T 1.41421356237309515f   // g = h/(||h||*sqrt(T)) so g.g' = sim
#define SIM_SCALE  60.0f                  // |sim| <= 2 -> |code| <= ~121 < 127
#define SIM_ISCALE (1.0f / 60.0f)

// ---------------- scratch (device globals; no allocation) ----------------
static __device__ __nv_bfloat16  d_Xb [(size_t)B_ * D_];     // bf16 X, 8 MB
static __device__ __nv_bfloat16  d_W1b[(size_t)D_ * D_];     // bf16 W1
static __device__ __nv_bfloat16  d_W2b[(size_t)PD_ * D_];    // bf16 W2
static __device__ __nv_bfloat16  d_A1b[(size_t)B_ * D_];     // relu(x@w1^T), 8 MB
static __device__ __nv_bfloat16  d_g  [(size_t)B_ * PD_];    // normalized h, 2 MB
static __device__ int8_t         d_sim[(size_t)B_ * B_];     // full symmetric, 67 MB
static __device__ float          d_partials[65536];
static __device__ unsigned int   d_done;

__device__ __forceinline__ uint32_t smem_addr(const void* p) {
    return (uint32_t)__cvta_generic_to_shared(p);
}
#define CP_ASYNC16(dst, src) \
    asm volatile("cp.async.cg.shared.global [%0], [%1], 16;" :: "r"(dst), "l"(src))
#define CP_COMMIT() asm volatile("cp.async.commit_group;" ::: "memory")
#define CP_WAIT1()  asm volatile("cp.async.wait_group 1;" ::: "memory")
#define CP_WAIT0()  asm volatile("cp.async.wait_group 0;" ::: "memory")

#define LDSM_X4(r0, r1, r2, r3, ad) \
    asm volatile("ldmatrix.sync.aligned.m8n8.x4.shared.b16 {%0,%1,%2,%3}, [%4];" \
                 : "=r"(r0), "=r"(r1), "=r"(r2), "=r"(r3) : "r"(ad))
#define MMA16816(acc, a, b) \
    asm volatile("mma.sync.aligned.m16n8k16.row.col.f32.bf16.bf16.f32 " \
                 "{%0,%1,%2,%3}, {%4,%5,%6,%7}, {%8,%9}, {%0,%1,%2,%3};" \
                 : "+f"((acc)[0]), "+f"((acc)[1]), "+f"((acc)[2]), "+f"((acc)[3]) \
                 : "r"((a)[0]), "r"((a)[1]), "r"((a)[2]), "r"((a)[3]), \
                   "r"((b)[0]), "r"((b)[1]))

// quantize 2 floats -> packed s8 pair in low 16 bits (byte0 = f0, byte1 = f1)
__device__ __forceinline__ uint32_t pack2_s8(float f0, float f1)
{
    int i0 = __float2int_rn(f0);
    int i1 = __float2int_rn(f1);
    uint32_t r;
    asm("cvt.pack.sat.s8.s32.b32 %0, %1, %2, 0;" : "=r"(r) : "r"(i1), "r"(i0));
    return r;
}

// =========================================================================
// Kernel 0: fp32 -> bf16 conversion of X, W1, W2 (one pass)
// =========================================================================
#define NX4  (B_ * D_ / 4)
#define NW14 (D_ * D_ / 4)
#define NW24 (PD_ * D_ / 4)
#define NCVT (NX4 + NW14 + NW24)

__global__ __launch_bounds__(256)
void convert_k(const float* __restrict__ X, const float* __restrict__ W1,
               const float* __restrict__ W2)
{
    int idx = blockIdx.x * 256 + threadIdx.x;
    if (idx >= NCVT) return;
    float4 v;
    __nv_bfloat16* dst;
    if (idx < NX4) {
        v = ((const float4*)X)[idx];
        dst = d_Xb + (size_t)idx * 4;
    } else if (idx < NX4 + NW14) {
        int j = idx - NX4;
        v = ((const float4*)W1)[j];
        dst = d_W1b + (size_t)j * 4;
    } else {
        int j = idx - NX4 - NW14;
        v = ((const float4*)W2)[j];
        dst = d_W2b + (size_t)j * 4;
    }
    __nv_bfloat162 p0 = __floats2bfloat162_rn(v.x, v.y);
    __nv_bfloat162 p1 = __floats2bfloat162_rn(v.z, v.w);
    uint2 o;
    o.x = *(uint32_t*)&p0;
    o.y = *(uint32_t*)&p1;
    *(uint2*)dst = o;
}

// =========================================================================
// Kernel 1: A1 = relu(X @ W1^T) bf16 HMMA + ldmatrix + cp.async (BK=64)
// =========================================================================
#define BSTR 72
#define G1_TILEE (128 * BSTR)
#define G1_SMEM_BYTES (4 * G1_TILEE * 2)

__global__ __launch_bounds__(256, 2)
void gemm1_bf16_k()
{
    extern __shared__ __nv_bfloat16 dynb[];
    __nv_bfloat16* Asb = dynb;
    __nv_bfloat16* Bsb = dynb + 2 * G1_TILEE;

    const int tid  = threadIdx.x;
    const int wid  = tid >> 5;
    const int lane = tid & 31;
    const int bm = blockIdx.y * 128;
    const int bn = blockIdx.x * 128;

    const int wm = (wid >> 2) * 64;
    const int wn = (wid & 3) * 32;
    const int qr = lane >> 2;
    const int qc2 = (lane & 3) * 2;

    const int a_row = lane & 15;
    const int a_kof = (lane >> 4) * 8;
    const int g3    = lane >> 3;
    const int b_row = 8 * (g3 >> 1) + (lane & 7);
    const int b_kof = 8 * (g3 & 1);

    int srow[4], scol[4];
#pragma unroll
    for (int l = 0; l < 4; l++) {
        int id = tid + l * 256;
        srow[l] = id >> 3;
        scol[l] = (id & 7) * 8;
    }

    float acc[4][4][4];
#pragma unroll
    for (int mi = 0; mi < 4; mi++)
#pragma unroll
        for (int nj = 0; nj < 4; nj++)
#pragma unroll
            for (int q = 0; q < 4; q++) acc[mi][nj][q] = 0.f;

#pragma unroll
    for (int l = 0; l < 4; l++) {
        CP_ASYNC16(smem_addr(Asb + srow[l] * BSTR + scol[l]),
                   d_Xb + (size_t)(bm + srow[l]) * D_ + scol[l]);
        CP_ASYNC16(smem_addr(Bsb + srow[l] * BSTR + scol[l]),
                   d_W1b + (size_t)(bn + srow[l]) * D_ + scol[l]);
    }
    CP_COMMIT();

    const int NIT = D_ / 64;
    for (int it = 0; it < NIT; it++) {
        if (it + 1 < NIT) {
            int kn = (it + 1) * 64;
            uint32_t boff = ((it + 1) & 1) * G1_TILEE;
#pragma unroll
            for (int l = 0; l < 4; l++) {
                CP_ASYNC16(smem_addr(Asb + boff + srow[l] * BSTR + scol[l]),
                           d_Xb + (size_t)(bm + srow[l]) * D_ + kn + scol[l]);
                CP_ASYNC16(smem_addr(Bsb + boff + srow[l] * BSTR + scol[l]),
                           d_W1b + (size_t)(bn + srow[l]) * D_ + kn + scol[l]);
            }
        }
        CP_COMMIT();
        CP_WAIT1();
        __syncthreads();

        const __nv_bfloat16* As = Asb + (it & 1) * G1_TILEE;
        const __nv_bfloat16* Bs = Bsb + (it & 1) * G1_TILEE;
#pragma unroll
        for (int ks = 0; ks < 4; ks++) {
            uint32_t a[4][4], b[4][2];
#pragma unroll
            for (int mi = 0; mi < 4; mi++) {
                uint32_t ad = smem_addr(As + (wm + 16 * mi + a_row) * BSTR
                                           + ks * 16 + a_kof);
                LDSM_X4(a[mi][0], a[mi][1], a[mi][2], a[mi][3], ad);
            }
#pragma unroll
            for (int nj2 = 0; nj2 < 2; nj2++) {
                uint32_t bd = smem_addr(Bs + (wn + 16 * nj2 + b_row) * BSTR
                                           + ks * 16 + b_kof);
                LDSM_X4(b[2 * nj2][0], b[2 * nj2][1],
                        b[2 * nj2 + 1][0], b[2 * nj2 + 1][1], bd);
            }
#pragma unroll
            for (int mi = 0; mi < 4; mi++)
#pragma unroll
                for (int nj = 0; nj < 4; nj++)
                    MMA16816(acc[mi][nj], a[mi], b[nj]);
        }
        __syncthreads();
    }

#pragma unroll
    for (int mi = 0; mi < 4; mi++)
#pragma unroll
        for (int nj = 0; nj < 4; nj++) {
            int row = bm + wm + 16 * mi + qr;
            int col = bn + wn + 8 * nj + qc2;
            __nv_bfloat162 lo = __floats2bfloat162_rn(fmaxf(acc[mi][nj][0], 0.f),
                                                      fmaxf(acc[mi][nj][1], 0.f));
            __nv_bfloat162 hi = __floats2bfloat162_rn(fmaxf(acc[mi][nj][2], 0.f),
                                                      fmaxf(acc[mi][nj][3], 0.f));
            *(__nv_bfloat162*)(d_A1b + (size_t)row * D_ + col) = lo;
            *(__nv_bfloat162*)(d_A1b + (size_t)(row + 8) * D_ + col) = hi;
        }
}

// =========================================================================
// Kernel 2: h = A1 @ W2^T bf16 HMMA + ldmatrix + cp.async, fused row-norm
// =========================================================================
#define G2_ATILEE (64 * BSTR)
#define G2_BTILEE (128 * BSTR)
#define G2_SMEM_BYTES (2 * (G2_ATILEE + G2_BTILEE) * 2)

__global__ __launch_bounds__(256, 2)
void gemm2_bf16_k()
{
    extern __shared__ __nv_bfloat16 dynb[];
    __nv_bfloat16* Asb = dynb;
    __nv_bfloat16* Bsb = dynb + 2 * G2_ATILEE;
    __shared__ float sqp[64][4];
    __shared__ float scale_s[64];

    const int tid  = threadIdx.x;
    const int wid  = tid >> 5;
    const int lane = tid & 31;
    const int bm = blockIdx.x * 64;

    const int wm = (wid >> 2) * 32;
    const int wn = (wid & 3) * 32;
    const int qr = lane >> 2;
    const int qc2 = (lane & 3) * 2;

    const int a_row = lane & 15;
    const int a_kof = (lane >> 4) * 8;
    const int g3    = lane >> 3;
    const int b_row = 8 * (g3 >> 1) + (lane & 7);
    const int b_kof = 8 * (g3 & 1);

    int srow[4], scol[4];
#pragma unroll
    for (int l = 0; l < 4; l++) {
        int id = tid + l * 256;
        srow[l] = id >> 3;
        scol[l] = (id & 7) * 8;
    }

    float acc[2][4][4];
#pragma unroll
    for (int mi = 0; mi < 2; mi++)
#pragma unroll
        for (int nj = 0; nj < 4; nj++)
#pragma unroll
            for (int q = 0; q < 4; q++) acc[mi][nj][q] = 0.f;

#pragma unroll
    for (int l = 0; l < 2; l++)
        CP_ASYNC16(smem_addr(Asb + srow[l] * BSTR + scol[l]),
                   d_A1b + (size_t)(bm + srow[l]) * D_ + scol[l]);
#pragma unroll
    for (int l = 0; l < 4; l++)
        CP_ASYNC16(smem_addr(Bsb + srow[l] * BSTR + scol[l]),
                   d_W2b + (size_t)srow[l] * D_ + scol[l]);
    CP_COMMIT();

    const int NIT = D_ / 64;
    for (int it = 0; it < NIT; it++) {
        if (it + 1 < NIT) {
            int kn = (it + 1) * 64;
            uint32_t ab = ((it + 1) & 1) * G2_ATILEE;
            uint32_t bb = ((it + 1) & 1) * G2_BTILEE;
#pragma unroll
            for (int l = 0; l < 2; l++)
                CP_ASYNC16(smem_addr(Asb + ab + srow[l] * BSTR + scol[l]),
                           d_A1b + (size_t)(bm + srow[l]) * D_ + kn + scol[l]);
#pragma unroll
            for (int l = 0; l < 4; l++)
                CP_ASYNC16(smem_addr(Bsb + bb + srow[l] * BSTR + scol[l]),
                           d_W2b + (size_t)srow[l] * D_ + kn + scol[l]);
        }
        CP_COMMIT();
        CP_WAIT1();
        __syncthreads();

        const __nv_bfloat16* As = Asb + (it & 1) * G2_ATILEE;
        const __nv_bfloat16* Bs = Bsb + (it & 1) * G2_BTILEE;
#pragma unroll
        for (int ks = 0; ks < 4; ks++) {
            uint32_t a[2][4], b[4][2];
#pragma unroll
            for (int mi = 0; mi < 2; mi++) {
                uint32_t ad = smem_addr(As + (wm + 16 * mi + a_row) * BSTR
                                           + ks * 16 + a_kof);
                LDSM_X4(a[mi][0], a[mi][1], a[mi][2], a[mi][3], ad);
            }
#pragma unroll
            for (int nj2 = 0; nj2 < 2; nj2++) {
                uint32_t bd = smem_addr(Bs + (wn + 16 * nj2 + b_row) * BSTR
                                           + ks * 16 + b_kof);
                LDSM_X4(b[2 * nj2][0], b[2 * nj2][1],
                        b[2 * nj2 + 1][0], b[2 * nj2 + 1][1], bd);
            }
#pragma unroll
            for (int mi = 0; mi < 2; mi++)
#pragma unroll
                for (int nj = 0; nj < 4; nj++)
                    MMA16816(acc[mi][nj], a[mi], b[nj]);
        }
        __syncthreads();
    }

#pragma unroll
    for (int mi = 0; mi < 2; mi++) {
        float s0 = 0.f, s1 = 0.f;
#pragma unroll
        for (int nj = 0; nj < 4; nj++) {
            s0 = fmaf(acc[mi][nj][0], acc[mi][nj][0], s0);
            s0 = fmaf(acc[mi][nj][1], acc[mi][nj][1], s0);
            s1 = fmaf(acc[mi][nj][2], acc[mi][nj][2], s1);
            s1 = fmaf(acc[mi][nj][3], acc[mi][nj][3], s1);
        }
        s0 += __shfl_xor_sync(0xffffffffu, s0, 1);
        s0 += __shfl_xor_sync(0xffffffffu, s0, 2);
        s1 += __shfl_xor_sync(0xffffffffu, s1, 1);
        s1 += __shfl_xor_sync(0xffffffffu, s1, 2);
        if ((lane & 3) == 0) {
            sqp[wm + 16 * mi + qr][wid & 3]     = s0;
            sqp[wm + 16 * mi + qr + 8][wid & 3] = s1;
        }
    }
    __syncthreads();
    if (tid < 64) {
        float ss = sqp[tid][0] + sqp[tid][1] + sqp[tid][2] + sqp[tid][3];
        scale_s[tid] = rsqrtf(fmaxf(ss, 1e-24f)) * INV_SQRT_T;
    }
    __syncthreads();

#pragma unroll
    for (int mi = 0; mi < 2; mi++)
#pragma unroll
        for (int nj = 0; nj < 4; nj++) {
            int r0 = wm + 16 * mi + qr;
            int col = wn + 8 * nj + qc2;
            float sc0 = scale_s[r0];
            float sc1 = scale_s[r0 + 8];
            __nv_bfloat162 lo = __floats2bfloat162_rn(acc[mi][nj][0] * sc0,
                                                      acc[mi][nj][1] * sc0);
            __nv_bfloat162 hi = __floats2bfloat162_rn(acc[mi][nj][2] * sc1,
                                                      acc[mi][nj][3] * sc1);
            *(__nv_bfloat162*)(d_g + (size_t)(bm + r0) * PD_ + col) = lo;
            *(__nv_bfloat162*)(d_g + (size_t)(bm + r0 + 8) * PD_ + col) = hi;
        }
}

// =========================================================================
// Kernel 3: Gram, triangular grid (2080 CTAs x 256 thr), bf16 HMMA.
// cp.async tile loads; register quant -> int8 SMEM staging (primary +
// transposed mirror) -> pure coalesced copy-outs.
// =========================================================================
#define TSTRIDE 136
#define ESTR 136
#define GRAM_SMEM_BYTES (2 * 128 * TSTRIDE * 2)   // 69632

__global__ __launch_bounds__(256, 2)
void gram_k()
{
    // triangular map: t -> (by, bx), bx >= by, 64x64 tile grid
    int t = blockIdx.x;
    int by = (int)(64.5f - sqrtf(64.5f * 64.5f - 2.0f * (float)t));
    while (by * 64 - by * (by - 1) / 2 > t) by--;
    while ((by + 1) * 64 - (by + 1) * by / 2 <= t) by++;
    int bx = by + (t - (by * 64 - by * (by - 1) / 2));

    extern __shared__ __nv_bfloat16 smg[];
    __nv_bfloat16* As = smg;
    __nv_bfloat16* Bs = smg + 128 * TSTRIDE;

    const int tid  = threadIdx.x;
    const int wid  = tid >> 5;
    const int lane = tid & 31;
    const int m0 = by * 128;
    const int n0 = bx * 128;
    const bool diag = (bx == by);

    // cp.async tile loads: 128 rows x 256B each, 16B chunks
#pragma unroll
    for (int i = 0; i < 8; i++) {
        int id = tid + i * 256;              // 0..2047
        int r  = id >> 4;
        int ch = id & 15;
        CP_ASYNC16(smem_addr(As + r * TSTRIDE + ch * 8),
                   d_g + (size_t)(m0 + r) * PD_ + ch * 8);
        CP_ASYNC16(smem_addr(Bs + r * TSTRIDE + ch * 8),
                   d_g + (size_t)(n0 + r) * PD_ + ch * 8);
    }
    CP_COMMIT();
    CP_WAIT0();
    __syncthreads();

    const int wm = (wid >> 2) * 64;
    const int wn = (wid & 3) * 32;
    const int qr = lane >> 2;
    const int qc = (lane & 3) * 2;

    const int a_row = lane & 15;
    const int a_kof = (lane >> 4) * 8;
    const int g3    = lane >> 3;
    const int b_row = 8 * (g3 >> 1) + (lane & 7);
    const int b_kof = 8 * (g3 & 1);

    float acc[4][4][4];
#pragma unroll
    for (int mi = 0; mi < 4; mi++)
#pragma unroll
        for (int nj = 0; nj < 4; nj++)
#pragma unroll
            for (int q = 0; q < 4; q++) acc[mi][nj][q] = 0.f;

#pragma unroll
    for (int ks = 0; ks < 8; ks++) {
        uint32_t a[4][4], b[4][2];
#pragma unroll
        for (int mi = 0; mi < 4; mi++) {
            uint32_t ad = smem_addr(As + (wm + 16 * mi + a_row) * TSTRIDE
                                       + ks * 16 + a_kof);
            LDSM_X4(a[mi][0], a[mi][1], a[mi][2], a[mi][3], ad);
        }
#pragma unroll
        for (int nj2 = 0; nj2 < 2; nj2++) {
            uint32_t bd = smem_addr(Bs + (wn + 16 * nj2 + b_row) * TSTRIDE
                                       + ks * 16 + b_kof);
            LDSM_X4(b[2 * nj2][0], b[2 * nj2][1],
                    b[2 * nj2 + 1][0], b[2 * nj2 + 1][1], bd);
        }
#pragma unroll
        for (int mi = 0; mi < 4; mi++)
#pragma unroll
            for (int nj = 0; nj < 4; nj++)
                MMA16816(acc[mi][nj], a[mi], b[nj]);
    }

    // ---- single-pass int8 staging: primary tile + transposed mirror ----
    __syncthreads();
    int8_t* ES  = (int8_t*)smg;              // [128][ESTR] (m-major)
    int8_t* EST = (int8_t*)smg + 128 * ESTR; // [128][ESTR] (n-major mirror)

#pragma unroll
    for (int mi = 0; mi < 4; mi++)
#pragma unroll
        for (int nj = 0; nj < 4; nj++) {
            int r0 = wm + 16 * mi + qr;
            int c0 = wn + 8 * nj + qc;
            uint32_t plo = pack2_s8(acc[mi][nj][0] * SIM_SCALE,
                                    acc[mi][nj][1] * SIM_SCALE);
            uint32_t phi = pack2_s8(acc[mi][nj][2] * SIM_SCALE,
                                    acc[mi][nj][3] * SIM_SCALE);
            *(uint16_t*)(ES + r0 * ESTR + c0)       = (uint16_t)plo;
            *(uint16_t*)(ES + (r0 + 8) * ESTR + c0) = (uint16_t)phi;
            if (!diag) {
                EST[c0 * ESTR + r0]           = (int8_t)(plo & 0xff);
                EST[(c0 + 1) * ESTR + r0]     = (int8_t)((plo >> 8) & 0xff);
                EST[c0 * ESTR + r0 + 8]       = (int8_t)(phi & 0xff);
                EST[(c0 + 1) * ESTR + r0 + 8] = (int8_t)((phi >> 8) & 0xff);
            }
        }
    __syncthreads();

    // ---- pure copy-outs (8B per thread-iter, fully coalesced) ----
#pragma unroll
    for (int i = 0; i < 8; i++) {
        int id = tid + i * 256;
        int r  = id >> 4;
        int ch = id & 15;
        uint2 v = *(const uint2*)(ES + r * ESTR + ch * 8);
        *(uint2*)(d_sim + (size_t)(m0 + r) * B_ + n0 + ch * 8) = v;
    }
    if (!diag) {
#pragma unroll
        for (int i = 0; i < 8; i++) {
            int id = tid + i * 256;
            int r  = id >> 4;
            int ch = id & 15;
            uint2 v = *(const uint2*)(EST + r * ESTR + ch * 8);
            *(uint2*)(d_sim + (size_t)(n0 + r) * B_ + m0 + ch * 8) = v;
        }
    }
}

// =========================================================================
// Kernel 4: gather + table-based logsumexp + fused deterministic finalize
// =========================================================================
__global__ __launch_bounds__(256)
void gather_lse_k(const int* __restrict__ anchors,
                  const int* __restrict__ positives,
                  const int* __restrict__ negidx,
                  int npairs, float* __restrict__ out)
{
    __shared__ float etab[256];
    __shared__ float ws[8];
    __shared__ int is_last;

    const int tid = threadIdx.x;
    etab[tid] = __expf((float)(tid - 128) * SIM_ISCALE);
    __syncthreads();

    const int p = blockIdx.x * 256 + tid;
    const bool valid = (p < npairs);
    const int pc = valid ? p : 0;

    const int a = anchors[pc];
    const int8_t* __restrict__ row = d_sim + (size_t)a * B_;
    int pidx = positives[pc];
    int nid[NNEG];
#pragma unroll
    for (int j = 0; j < NNEG; j++) nid[j] = negidx[(size_t)pc * NNEG + j];

    int cp = (int)row[pidx];
    float sum = etab[cp + 128];
#pragma unroll
    for (int j = 0; j < NNEG; j++) sum += etab[(int)row[nid[j]] + 128];

    float contrib = valid ? (__logf(sum) - (float)cp * SIM_ISCALE) : 0.f;

    contrib += __shfl_xor_sync(0xffffffffu, contrib, 1);
    contrib += __shfl_xor_sync(0xffffffffu, contrib, 2);
    contrib += __shfl_xor_sync(0xffffffffu, contrib, 4);
    contrib += __shfl_xor_sync(0xffffffffu, contrib, 8);
    contrib += __shfl_xor_sync(0xffffffffu, contrib, 16);
    if ((tid & 31) == 0) ws[tid >> 5] = contrib;
    __syncthreads();
    if (tid < 8) {
        float cv = ws[tid];
        cv += __shfl_xor_sync(0xffu, cv, 1);
        cv += __shfl_xor_sync(0xffu, cv, 2);
        cv += __shfl_xor_sync(0xffu, cv, 4);
        if (tid == 0) d_partials[blockIdx.x] = cv;
    }

    if (tid == 0) {
        __threadfence();
        unsigned t = atomicAdd(&d_done, 1u);
        is_last = (t == gridDim.x - 1);
    }
    __syncthreads();
    if (is_last) {
        __shared__ float sm[256];
        float s = 0.f;
        for (int i = tid; i < (int)gridDim.x; i += 256) s += d_partials[i];
        sm[tid] = s;
        __syncthreads();
        for (int w = 128; w > 0; w >>= 1) {
            if (tid < w) sm[tid] += sm[tid + w];
            __syncthreads();
        }
        if (tid == 0) {
            out[0] = sm[0] / (float)npairs;
            d_done = 0;
        }
    }
}

// =========================================================================
extern "C" void kernel_launch(void* const* d_in, const int* in_sizes, int n_in,
                              void* d_out, int out_size)
{
    const float* x        = (const float*)d_in[0];
    const float* w1       = (const float*)d_in[1];
    const float* w2       = (const float*)d_in[2];
    const int*   anchors  = (const int*)d_in[4];
    const int*   positives= (const int*)d_in[5];
    const int*   negidx   = (const int*)d_in[6];
    const int npairs = in_sizes[4];

    static int attrs_set = 0;
    if (!attrs_set) {
        cudaFuncSetAttribute(gemm1_bf16_k,
                             cudaFuncAttributeMaxDynamicSharedMemorySize, G1_SMEM_BYTES);
        cudaFuncSetAttribute(gemm2_bf16_k,
                             cudaFuncAttributeMaxDynamicSharedMemorySize, G2_SMEM_BYTES);
        cudaFuncSetAttribute(gram_k,
                             cudaFuncAttributeMaxDynamicSharedMemorySize, GRAM_SMEM_BYTES);
        attrs_set = 1;
    }

    convert_k<<<(NCVT + 255) / 256, 256>>>(x, w1, w2);

    dim3 g1(D_ / 128, B_ / 128);
    gemm1_bf16_k<<<g1, 256, G1_SMEM_BYTES>>>();

    gemm2_bf16_k<<<B_ / 64, 256, G2_SMEM_BYTES>>>();

    gram_k<<<2080, 256, GRAM_SMEM_BYTES>>>();   // 64*65/2 upper tiles

    int pblocks = (npairs + 255) / 256;
    gather_lse_k<<<pblocks, 256>>>(anchors, positives, negidx, npairs,
                                   (float*)d_out);
}

// round 16
// speedup vs baseline: 1.2232x; 1.0024x over previous
#include <cuda_runtime.h>
#include <cuda_bf16.h>
#include <cstdint>

#define B_   8192
#define D_   512
#define PD_  128
#define NNEG 10
#define INV_SQRT_T 1.41421356237309515f   // g = h/(||h||*sqrt(T)) so g.g' = sim
#define SIM_SCALE  60.0f
#define SIM_ISCALE (1.0f / 60.0f)

// ---------------- scratch (device globals; no allocation) ----------------
static __device__ __nv_bfloat16  d_Xb [(size_t)B_ * D_];
static __device__ __nv_bfloat16  d_W1b[(size_t)D_ * D_];
static __device__ __nv_bfloat16  d_W2b[(size_t)PD_ * D_];
static __device__ __nv_bfloat16  d_A1b[(size_t)B_ * D_];
static __device__ __nv_bfloat16  d_g  [(size_t)B_ * PD_];
static __device__ int8_t         d_sim[(size_t)B_ * B_];
static __device__ float          d_partials[65536];
static __device__ unsigned int   d_done;

__device__ __forceinline__ uint32_t smem_addr(const void* p) {
    return (uint32_t)__cvta_generic_to_shared(p);
}
#define CP_ASYNC16(dst, src) \
    asm volatile("cp.async.cg.shared.global [%0], [%1], 16;" :: "r"(dst), "l"(src))
#define CP_COMMIT() asm volatile("cp.async.commit_group;" ::: "memory")
#define CP_WAIT1()  asm volatile("cp.async.wait_group 1;" ::: "memory")
#define CP_WAIT0()  asm volatile("cp.async.wait_group 0;" ::: "memory")

#define LDSM_X4(r0, r1, r2, r3, ad) \
    asm volatile("ldmatrix.sync.aligned.m8n8.x4.shared.b16 {%0,%1,%2,%3}, [%4];" \
                 : "=r"(r0), "=r"(r1), "=r"(r2), "=r"(r3) : "r"(ad))
#define MMA16816(acc, a, b) \
    asm volatile("mma.sync.aligned.m16n8k16.row.col.f32.bf16.bf16.f32 " \
                 "{%0,%1,%2,%3}, {%4,%5,%6,%7}, {%8,%9}, {%0,%1,%2,%3};" \
                 : "+f"((acc)[0]), "+f"((acc)[1]), "+f"((acc)[2]), "+f"((acc)[3]) \
                 : "r"((a)[0]), "r"((a)[1]), "r"((a)[2]), "r"((a)[3]), \
                   "r"((b)[0]), "r"((b)[1]))

__device__ __forceinline__ uint32_t pack2_s8(float f0, float f1)
{
    int i0 = __float2int_rn(f0);
    int i1 = __float2int_rn(f1);
    uint32_t r;
    asm("cvt.pack.sat.s8.s32.b32 %0, %1, %2, 0;" : "=r"(r) : "r"(i1), "r"(i0));
    return r;
}

// =========================================================================
// Kernel 0: fp32 -> bf16 conversion of X, W1, W2 (one pass)
// =========================================================================
#define NX4  (B_ * D_ / 4)
#define NW14 (D_ * D_ / 4)
#define NW24 (PD_ * D_ / 4)
#define NCVT (NX4 + NW14 + NW24)

__global__ __launch_bounds__(256)
void convert_k(const float* __restrict__ X, const float* __restrict__ W1,
               const float* __restrict__ W2)
{
    int idx = blockIdx.x * 256 + threadIdx.x;
    if (idx >= NCVT) return;
    float4 v;
    __nv_bfloat16* dst;
    if (idx < NX4) {
        v = ((const float4*)X)[idx];
        dst = d_Xb + (size_t)idx * 4;
    } else if (idx < NX4 + NW14) {
        int j = idx - NX4;
        v = ((const float4*)W1)[j];
        dst = d_W1b + (size_t)j * 4;
    } else {
        int j = idx - NX4 - NW14;
        v = ((const float4*)W2)[j];
        dst = d_W2b + (size_t)j * 4;
    }
    __nv_bfloat162 p0 = __floats2bfloat162_rn(v.x, v.y);
    __nv_bfloat162 p1 = __floats2bfloat162_rn(v.z, v.w);
    uint2 o;
    o.x = *(uint32_t*)&p0;
    o.y = *(uint32_t*)&p1;
    *(uint2*)dst = o;
}

// =========================================================================
// Kernel 1: A1 = relu(X @ W1^T), 3-stage cp.async pipeline, 1 sync/iter
// 128x128 CTA tile, BK=64, 8 warps (2x4), warp tile 64x32.
// =========================================================================
#define BSTR 72
#define G1_TILEE (128 * BSTR)
#define G1_SMEM_BYTES (3 * 2 * G1_TILEE * 2)       // 110592 B

__global__ __launch_bounds__(256, 2)
void gemm1_bf16_k()
{
    extern __shared__ __nv_bfloat16 dynb[];
    __nv_bfloat16* Asb = dynb;                     // [3][128*BSTR]
    __nv_bfloat16* Bsb = dynb + 3 * G1_TILEE;      // [3][128*BSTR]

    const int tid  = threadIdx.x;
    const int wid  = tid >> 5;
    const int lane = tid & 31;
    const int bm = blockIdx.y * 128;
    const int bn = blockIdx.x * 128;

    const int wm = (wid >> 2) * 64;
    const int wn = (wid & 3) * 32;
    const int qr = lane >> 2;
    const int qc2 = (lane & 3) * 2;

    const int a_row = lane & 15;
    const int a_kof = (lane >> 4) * 8;
    const int g3    = lane >> 3;
    const int b_row = 8 * (g3 >> 1) + (lane & 7);
    const int b_kof = 8 * (g3 & 1);

    int srow[4], scol[4];
#pragma unroll
    for (int l = 0; l < 4; l++) {
        int id = tid + l * 256;
        srow[l] = id >> 3;
        scol[l] = (id & 7) * 8;
    }

    float acc[4][4][4];
#pragma unroll
    for (int mi = 0; mi < 4; mi++)
#pragma unroll
        for (int nj = 0; nj < 4; nj++)
#pragma unroll
            for (int q = 0; q < 4; q++) acc[mi][nj][q] = 0.f;

    // prologue: stages 0 and 1
#pragma unroll
    for (int s = 0; s < 2; s++) {
        int kn = s * 64;
#pragma unroll
        for (int l = 0; l < 4; l++) {
            CP_ASYNC16(smem_addr(Asb + s * G1_TILEE + srow[l] * BSTR + scol[l]),
                       d_Xb + (size_t)(bm + srow[l]) * D_ + kn + scol[l]);
            CP_ASYNC16(smem_addr(Bsb + s * G1_TILEE + srow[l] * BSTR + scol[l]),
                       d_W1b + (size_t)(bn + srow[l]) * D_ + kn + scol[l]);
        }
        CP_COMMIT();
    }

    const int NIT = D_ / 64;                        // 8
    for (int it = 0; it < NIT; it++) {
        CP_WAIT1();                                 // stage it complete
        __syncthreads();                            // closes reads of stage it-1

        if (it + 2 < NIT) {
            int kn = (it + 2) * 64;
            int sb = (it + 2) % 3;
#pragma unroll
            for (int l = 0; l < 4; l++) {
                CP_ASYNC16(smem_addr(Asb + sb * G1_TILEE + srow[l] * BSTR + scol[l]),
                           d_Xb + (size_t)(bm + srow[l]) * D_ + kn + scol[l]);
                CP_ASYNC16(smem_addr(Bsb + sb * G1_TILEE + srow[l] * BSTR + scol[l]),
                           d_W1b + (size_t)(bn + srow[l]) * D_ + kn + scol[l]);
            }
        }
        CP_COMMIT();                                // (empty group ok)

        const __nv_bfloat16* As = Asb + (it % 3) * G1_TILEE;
        const __nv_bfloat16* Bs = Bsb + (it % 3) * G1_TILEE;
#pragma unroll
        for (int ks = 0; ks < 4; ks++) {
            uint32_t a[4][4], b[4][2];
#pragma unroll
            for (int mi = 0; mi < 4; mi++) {
                uint32_t ad = smem_addr(As + (wm + 16 * mi + a_row) * BSTR
                                           + ks * 16 + a_kof);
                LDSM_X4(a[mi][0], a[mi][1], a[mi][2], a[mi][3], ad);
            }
#pragma unroll
            for (int nj2 = 0; nj2 < 2; nj2++) {
                uint32_t bd = smem_addr(Bs + (wn + 16 * nj2 + b_row) * BSTR
                                           + ks * 16 + b_kof);
                LDSM_X4(b[2 * nj2][0], b[2 * nj2][1],
                        b[2 * nj2 + 1][0], b[2 * nj2 + 1][1], bd);
            }
#pragma unroll
            for (int mi = 0; mi < 4; mi++)
#pragma unroll
                for (int nj = 0; nj < 4; nj++)
                    MMA16816(acc[mi][nj], a[mi], b[nj]);
        }
    }

#pragma unroll
    for (int mi = 0; mi < 4; mi++)
#pragma unroll
        for (int nj = 0; nj < 4; nj++) {
            int row = bm + wm + 16 * mi + qr;
            int col = bn + wn + 8 * nj + qc2;
            __nv_bfloat162 lo = __floats2bfloat162_rn(fmaxf(acc[mi][nj][0], 0.f),
                                                      fmaxf(acc[mi][nj][1], 0.f));
            __nv_bfloat162 hi = __floats2bfloat162_rn(fmaxf(acc[mi][nj][2], 0.f),
                                                      fmaxf(acc[mi][nj][3], 0.f));
            *(__nv_bfloat162*)(d_A1b + (size_t)row * D_ + col) = lo;
            *(__nv_bfloat162*)(d_A1b + (size_t)(row + 8) * D_ + col) = hi;
        }
}

// =========================================================================
// Kernel 2: h = A1 @ W2^T, 32-row CTA tiles (256 CTAs), 3-stage pipeline,
// fused row-norm -> g (bf16). 8 warps (2x4), warp tile 16x32.
// =========================================================================
#define G2_AST (32 * BSTR)                          // 2304 elems
#define G2_BST (128 * BSTR)                         // 9216 elems
#define G2_SMEM_BYTES (3 * (G2_AST + G2_BST) * 2)   // 69120 B

__global__ __launch_bounds__(256, 2)
void gemm2_bf16_k()
{
    extern __shared__ __nv_bfloat16 dynb[];
    __nv_bfloat16* Asb = dynb;                      // [3][32*BSTR]
    __nv_bfloat16* Bsb = dynb + 3 * G2_AST;         // [3][128*BSTR]
    __shared__ float sqp[32][4];
    __shared__ float scale_s[32];

    const int tid  = threadIdx.x;
    const int wid  = tid >> 5;
    const int lane = tid & 31;
    const int bm = blockIdx.x * 32;

    const int wm = (wid >> 2) * 16;                 // 0 or 16
    const int wn = (wid & 3) * 32;
    const int qr = lane >> 2;
    const int qc2 = (lane & 3) * 2;

    const int a_row = lane & 15;
    const int a_kof = (lane >> 4) * 8;
    const int g3    = lane >> 3;
    const int b_row = 8 * (g3 >> 1) + (lane & 7);
    const int b_kof = 8 * (g3 & 1);

    // staging coords: A one chunk/thread (32x8), B four chunks/thread
    const int ar = tid >> 3;                        // 0..31
    const int ac = (tid & 7) * 8;
    int srow[4], scol[4];
#pragma unroll
    for (int l = 0; l < 4; l++) {
        int id = tid + l * 256;
        srow[l] = id >> 3;
        scol[l] = (id & 7) * 8;
    }

    float acc[4][4];
#pragma unroll
    for (int nj = 0; nj < 4; nj++)
#pragma unroll
        for (int q = 0; q < 4; q++) acc[nj][q] = 0.f;

    // prologue: stages 0 and 1
#pragma unroll
    for (int s = 0; s < 2; s++) {
        int kn = s * 64;
        CP_ASYNC16(smem_addr(Asb + s * G2_AST + ar * BSTR + ac),
                   d_A1b + (size_t)(bm + ar) * D_ + kn + ac);
#pragma unroll
        for (int l = 0; l < 4; l++)
            CP_ASYNC16(smem_addr(Bsb + s * G2_BST + srow[l] * BSTR + scol[l]),
                       d_W2b + (size_t)srow[l] * D_ + kn + scol[l]);
        CP_COMMIT();
    }

    const int NIT = D_ / 64;
    for (int it = 0; it < NIT; it++) {
        CP_WAIT1();
        __syncthreads();

        if (it + 2 < NIT) {
            int kn = (it + 2) * 64;
            int sb = (it + 2) % 3;
            CP_ASYNC16(smem_addr(Asb + sb * G2_AST + ar * BSTR + ac),
                       d_A1b + (size_t)(bm + ar) * D_ + kn + ac);
#pragma unroll
            for (int l = 0; l < 4; l++)
                CP_ASYNC16(smem_addr(Bsb + sb * G2_BST + srow[l] * BSTR + scol[l]),
                           d_W2b + (size_t)srow[l] * D_ + kn + scol[l]);
        }
        CP_COMMIT();

        const __nv_bfloat16* As = Asb + (it % 3) * G2_AST;
        const __nv_bfloat16* Bs = Bsb + (it % 3) * G2_BST;
#pragma unroll
        for (int ks = 0; ks < 4; ks++) {
            uint32_t a[4], b[4][2];
            {
                uint32_t ad = smem_addr(As + (wm + a_row) * BSTR
                                           + ks * 16 + a_kof);
                LDSM_X4(a[0], a[1], a[2], a[3], ad);
            }
#pragma unroll
            for (int nj2 = 0; nj2 < 2; nj2++) {
                uint32_t bd = smem_addr(Bs + (wn + 16 * nj2 + b_row) * BSTR
                                           + ks * 16 + b_kof);
                LDSM_X4(b[2 * nj2][0], b[2 * nj2][1],
                        b[2 * nj2 + 1][0], b[2 * nj2 + 1][1], bd);
            }
#pragma unroll
            for (int nj = 0; nj < 4; nj++)
                MMA16816(acc[nj], a, b[nj]);
        }
    }

    // ---- fused row-norm over 32 rows ----
    {
        float s0 = 0.f, s1 = 0.f;
#pragma unroll
        for (int nj = 0; nj < 4; nj++) {
            s0 = fmaf(acc[nj][0], acc[nj][0], s0);
            s0 = fmaf(acc[nj][1], acc[nj][1], s0);
            s1 = fmaf(acc[nj][2], acc[nj][2], s1);
            s1 = fmaf(acc[nj][3], acc[nj][3], s1);
        }
        s0 += __shfl_xor_sync(0xffffffffu, s0, 1);
        s0 += __shfl_xor_sync(0xffffffffu, s0, 2);
        s1 += __shfl_xor_sync(0xffffffffu, s1, 1);
        s1 += __shfl_xor_sync(0xffffffffu, s1, 2);
        if ((lane & 3) == 0) {
            sqp[wm + qr][wid & 3]     = s0;
            sqp[wm + qr + 8][wid & 3] = s1;
        }
    }
    __syncthreads();
    if (tid < 32) {
        float ss = sqp[tid][0] + sqp[tid][1] + sqp[tid][2] + sqp[tid][3];
        scale_s[tid] = rsqrtf(fmaxf(ss, 1e-24f)) * INV_SQRT_T;
    }
    __syncthreads();

#pragma unroll
    for (int nj = 0; nj < 4; nj++) {
        int r0 = wm + qr;
        int col = wn + 8 * nj + qc2;
        float sc0 = scale_s[r0];
        float sc1 = scale_s[r0 + 8];
        __nv_bfloat162 lo = __floats2bfloat162_rn(acc[nj][0] * sc0,
                                                  acc[nj][1] * sc0);
        __nv_bfloat162 hi = __floats2bfloat162_rn(acc[nj][2] * sc1,
                                                  acc[nj][3] * sc1);
        *(__nv_bfloat162*)(d_g + (size_t)(bm + r0) * PD_ + col) = lo;
        *(__nv_bfloat162*)(d_g + (size_t)(bm + r0 + 8) * PD_ + col) = hi;
    }
}

// =========================================================================
// Kernel 3: Gram, triangular grid (2080 CTAs x 256 thr), bf16 HMMA.
// (at mma.sync plateau — unchanged from R15)
// =========================================================================
#define TSTRIDE 136
#define ESTR 136
#define GRAM_SMEM_BYTES (2 * 128 * TSTRIDE * 2)

__global__ __launch_bounds__(256, 2)
void gram_k()
{
    int t = blockIdx.x;
    int by = (int)(64.5f - sqrtf(64.5f * 64.5f - 2.0f * (float)t));
    while (by * 64 - by * (by - 1) / 2 > t) by--;
    while ((by + 1) * 64 - (by + 1) * by / 2 <= t) by++;
    int bx = by + (t - (by * 64 - by * (by - 1) / 2));

    extern __shared__ __nv_bfloat16 smg[];
    __nv_bfloat16* As = smg;
    __nv_bfloat16* Bs = smg + 128 * TSTRIDE;

    const int tid  = threadIdx.x;
    const int wid  = tid >> 5;
    const int lane = tid & 31;
    const int m0 = by * 128;
    const int n0 = bx * 128;
    const bool diag = (bx == by);

#pragma unroll
    for (int i = 0; i < 8; i++) {
        int id = tid + i * 256;
        int r  = id >> 4;
        int ch = id & 15;
        CP_ASYNC16(smem_addr(As + r * TSTRIDE + ch * 8),
                   d_g + (size_t)(m0 + r) * PD_ + ch * 8);
        CP_ASYNC16(smem_addr(Bs + r * TSTRIDE + ch * 8),
                   d_g + (size_t)(n0 + r) * PD_ + ch * 8);
    }
    CP_COMMIT();
    CP_WAIT0();
    __syncthreads();

    const int wm = (wid >> 2) * 64;
    const int wn = (wid & 3) * 32;
    const int qr = lane >> 2;
    const int qc = (lane & 3) * 2;

    const int a_row = lane & 15;
    const int a_kof = (lane >> 4) * 8;
    const int g3    = lane >> 3;
    const int b_row = 8 * (g3 >> 1) + (lane & 7);
    const int b_kof = 8 * (g3 & 1);

    float acc[4][4][4];
#pragma unroll
    for (int mi = 0; mi < 4; mi++)
#pragma unroll
        for (int nj = 0; nj < 4; nj++)
#pragma unroll
            for (int q = 0; q < 4; q++) acc[mi][nj][q] = 0.f;

#pragma unroll
    for (int ks = 0; ks < 8; ks++) {
        uint32_t a[4][4], b[4][2];
#pragma unroll
        for (int mi = 0; mi < 4; mi++) {
            uint32_t ad = smem_addr(As + (wm + 16 * mi + a_row) * TSTRIDE
                                       + ks * 16 + a_kof);
            LDSM_X4(a[mi][0], a[mi][1], a[mi][2], a[mi][3], ad);
        }
#pragma unroll
        for (int nj2 = 0; nj2 < 2; nj2++) {
            uint32_t bd = smem_addr(Bs + (wn + 16 * nj2 + b_row) * TSTRIDE
                                       + ks * 16 + b_kof);
            LDSM_X4(b[2 * nj2][0], b[2 * nj2][1],
                    b[2 * nj2 + 1][0], b[2 * nj2 + 1][1], bd);
        }
#pragma unroll
        for (int mi = 0; mi < 4; mi++)
#pragma unroll
            for (int nj = 0; nj < 4; nj++)
                MMA16816(acc[mi][nj], a[mi], b[nj]);
    }

    __syncthreads();
    int8_t* ES  = (int8_t*)smg;
    int8_t* EST = (int8_t*)smg + 128 * ESTR;

#pragma unroll
    for (int mi = 0; mi < 4; mi++)
#pragma unroll
        for (int nj = 0; nj < 4; nj++) {
            int r0 = wm + 16 * mi + qr;
            int c0 = wn + 8 * nj + qc;
            uint32_t plo = pack2_s8(acc[mi][nj][0] * SIM_SCALE,
                                    acc[mi][nj][1] * SIM_SCALE);
            uint32_t phi = pack2_s8(acc[mi][nj][2] * SIM_SCALE,
                                    acc[mi][nj][3] * SIM_SCALE);
            *(uint16_t*)(ES + r0 * ESTR + c0)       = (uint16_t)plo;
            *(uint16_t*)(ES + (r0 + 8) * ESTR + c0) = (uint16_t)phi;
            if (!diag) {
                EST[c0 * ESTR + r0]           = (int8_t)(plo & 0xff);
                EST[(c0 + 1) * ESTR + r0]     = (int8_t)((plo >> 8) & 0xff);
                EST[c0 * ESTR + r0 + 8]       = (int8_t)(phi & 0xff);
                EST[(c0 + 1) * ESTR + r0 + 8] = (int8_t)((phi >> 8) & 0xff);
            }
        }
    __syncthreads();

#pragma unroll
    for (int i = 0; i < 8; i++) {
        int id = tid + i * 256;
        int r  = id >> 4;
        int ch = id & 15;
        uint2 v = *(const uint2*)(ES + r * ESTR + ch * 8);
        *(uint2*)(d_sim + (size_t)(m0 + r) * B_ + n0 + ch * 8) = v;
    }
    if (!diag) {
#pragma unroll
        for (int i = 0; i < 8; i++) {
            int id = tid + i * 256;
            int r  = id >> 4;
            int ch = id & 15;
            uint2 v = *(const uint2*)(EST + r * ESTR + ch * 8);
            *(uint2*)(d_sim + (size_t)(n0 + r) * B_ + m0 + ch * 8) = v;
        }
    }
}

// =========================================================================
// Kernel 4: gather + table-based logsumexp + fused deterministic finalize
// =========================================================================
__global__ __launch_bounds__(256)
void gather_lse_k(const int* __restrict__ anchors,
                  const int* __restrict__ positives,
                  const int* __restrict__ negidx,
                  int npairs, float* __restrict__ out)
{
    __shared__ float etab[256];
    __shared__ float ws[8];
    __shared__ int is_last;

    const int tid = threadIdx.x;
    etab[tid] = __expf((float)(tid - 128) * SIM_ISCALE);
    __syncthreads();

    const int p = blockIdx.x * 256 + tid;
    const bool valid = (p < npairs);
    const int pc = valid ? p : 0;

    const int a = anchors[pc];
    const int8_t* __restrict__ row = d_sim + (size_t)a * B_;
    int pidx = positives[pc];
    int nid[NNEG];
#pragma unroll
    for (int j = 0; j < NNEG; j++) nid[j] = negidx[(size_t)pc * NNEG + j];

    int cp = (int)row[pidx];
    float sum = etab[cp + 128];
#pragma unroll
    for (int j = 0; j < NNEG; j++) sum += etab[(int)row[nid[j]] + 128];

    float contrib = valid ? (__logf(sum) - (float)cp * SIM_ISCALE) : 0.f;

    contrib += __shfl_xor_sync(0xffffffffu, contrib, 1);
    contrib += __shfl_xor_sync(0xffffffffu, contrib, 2);
    contrib += __shfl_xor_sync(0xffffffffu, contrib, 4);
    contrib += __shfl_xor_sync(0xffffffffu, contrib, 8);
    contrib += __shfl_xor_sync(0xffffffffu, contrib, 16);
    if ((tid & 31) == 0) ws[tid >> 5] = contrib;
    __syncthreads();
    if (tid < 8) {
        float cv = ws[tid];
        cv += __shfl_xor_sync(0xffu, cv, 1);
        cv += __shfl_xor_sync(0xffu, cv, 2);
        cv += __shfl_xor_sync(0xffu, cv, 4);
        if (tid == 0) d_partials[blockIdx.x] = cv;
    }

    if (tid == 0) {
        __threadfence();
        unsigned t = atomicAdd(&d_done, 1u);
        is_last = (t == gridDim.x - 1);
    }
    __syncthreads();
    if (is_last) {
        __shared__ float sm[256];
        float s = 0.f;
        for (int i = tid; i < (int)gridDim.x; i += 256) s += d_partials[i];
        sm[tid] = s;
        __syncthreads();
        for (int w = 128; w > 0; w >>= 1) {
            if (tid < w) sm[tid] += sm[tid + w];
            __syncthreads();
        }
        if (tid == 0) {
            out[0] = sm[0] / (float)npairs;
            d_done = 0;
        }
    }
}

// =========================================================================
extern "C" void kernel_launch(void* const* d_in, const int* in_sizes, int n_in,
                              void* d_out, int out_size)
{
    const float* x        = (const float*)d_in[0];
    const float* w1       = (const float*)d_in[1];
    const float* w2       = (const float*)d_in[2];
    const int*   anchors  = (const int*)d_in[4];
    const int*   positives= (const int*)d_in[5];
    const int*   negidx   = (const int*)d_in[6];
    const int npairs = in_sizes[4];

    static int attrs_set = 0;
    if (!attrs_set) {
        cudaFuncSetAttribute(gemm1_bf16_k,
                             cudaFuncAttributeMaxDynamicSharedMemorySize, G1_SMEM_BYTES);
        cudaFuncSetAttribute(gemm2_bf16_k,
                             cudaFuncAttributeMaxDynamicSharedMemorySize, G2_SMEM_BYTES);
        cudaFuncSetAttribute(gram_k,
                             cudaFuncAttributeMaxDynamicSharedMemorySize, GRAM_SMEM_BYTES);
        attrs_set = 1;
    }

    convert_k<<<(NCVT + 255) / 256, 256>>>(x, w1, w2);

    dim3 g1(D_ / 128, B_ / 128);
    gemm1_bf16_k<<<g1, 256, G1_SMEM_BYTES>>>();

    gemm2_bf16_k<<<B_ / 32, 256, G2_SMEM_BYTES>>>();   // 256 CTAs

    gram_k<<<2080, 256, GRAM_SMEM_BYTES>>>();

    int pblocks = (npairs + 255) / 256;
    gather_lse_k<<<pblocks, 256>>>(anchors, positives, negidx, npairs,
                                   (float*)d_out);
}